// round 14
// baseline (speedup 1.0000x reference)
#include <cuda_runtime.h>
#include <cuda_bf16.h>
#include <cstdint>
#include <math.h>

typedef __nv_bfloat16 bf16;

// ---------------- Problem constants ----------------
#define BATCH 2
#define SEQ 2048
#define BS 4096
#define DIM 1024
#define NH 8
#define QC 128
#define QNOPE 96
#define QROPE 32
#define KVC 128
#define KNOPE 64
#define KROPE 64
#define VHD 256
#define DQK 128
#define NCOMB 320                      // QC + KVC + KROPE
#define EPSV 1e-8f
#define SOFTMAX_SCALE 0.08838834764831845f

// ---------------- Scratch (device globals) ----------------
__device__ float g_comb[BS * NCOMB];               // [dq(128) | ckv(128) | krope(64)]
__device__ float g_q[BS * NH * DQK];
__device__ float g_ckv[BS * KVC];
__device__ float g_kv[BS * (NH * KNOPE)];
__device__ float g_Wf[DIM * DIM];
__device__ float g_bias_eff[DIM];
__device__ float g_bcomb[NCOMB];

__device__ bf16 g_Sh[16 * SEQ * SEQ], g_Sl[16 * SEQ * SEQ];   // 128 MB scores (hi/lo)
__device__ bf16 g_xh[BS * DIM],  g_xl[BS * DIM];
__device__ bf16 g_cqh[BS * QC],  g_cql[BS * QC];
__device__ bf16 g_ckvh[BS * KVC], g_ckvl[BS * KVC];
__device__ bf16 g_ckvTh[BATCH * KVC * SEQ], g_ckvTl[BATCH * KVC * SEQ];
__device__ bf16 g_Qh[BATCH * NH * SEQ * DQK], g_Ql[BATCH * NH * SEQ * DQK];
__device__ bf16 g_Kh[BATCH * NH * SEQ * DQK], g_Kl[BATCH * NH * SEQ * DQK];
__device__ bf16 g_Ph[16 * SEQ * SEQ], g_Pl[16 * SEQ * SEQ];
__device__ bf16 g_ctxh[BS * NH * KVC], g_ctxl[BS * NH * KVC];
__device__ bf16 g_wcombh[NCOMB * DIM], g_wcombl[NCOMB * DIM];   // transposed dq|dkv
__device__ bf16 g_wuqh[NH * DQK * QC], g_wuql[NH * DQK * QC];
__device__ bf16 g_wukvh[(NH * KNOPE) * KVC], g_wukvl[(NH * KNOPE) * KVC];
__device__ bf16 g_wukvnth[KVC * (NH * (KNOPE + VHD))], g_wukvntl[KVC * (NH * (KNOPE + VHD))];
__device__ bf16 g_woh[DIM * NH * VHD], g_wol[DIM * NH * VHD];
__device__ bf16 g_WfBh[DIM * DIM], g_WfBl[DIM * DIM];

__device__ __forceinline__ void bsplit(float x, bf16& h, bf16& l) {
    h = __float2bfloat16(x);
    l = __float2bfloat16(x - __bfloat162float(h));
}
__device__ __forceinline__ uint32_t smem_u32(const void* p) {
    uint32_t a;
    asm("{ .reg .u64 t; cvta.to.shared.u64 t, %1; cvt.u32.u64 %0, t; }" : "=r"(a) : "l"(p));
    return a;
}
__device__ __forceinline__ void cp16(uint32_t s, const void* g) {
    asm volatile("cp.async.ca.shared.global [%0], [%1], 16;" :: "r"(s), "l"(g));
}
#define CP_COMMIT() asm volatile("cp.async.commit_group;" ::: "memory")
#define CP_WAIT0()  asm volatile("cp.async.wait_group 0;" ::: "memory")
#define CP_WAIT1()  asm volatile("cp.async.wait_group 1;" ::: "memory")

__device__ __forceinline__ void lds4(uint32_t addr, uint32_t* r) {
    asm volatile("ldmatrix.sync.aligned.m8n8.x4.shared.b16 {%0,%1,%2,%3}, [%4];"
                 : "=r"(r[0]), "=r"(r[1]), "=r"(r[2]), "=r"(r[3]) : "r"(addr));
}
__device__ __forceinline__ void mma16816(float* c, const uint32_t* a, uint32_t b0, uint32_t b1) {
    asm volatile("mma.sync.aligned.m16n8k16.row.col.f32.bf16.bf16.f32 "
                 "{%0,%1,%2,%3}, {%4,%5,%6,%7}, {%8,%9}, {%0,%1,%2,%3};"
                 : "+f"(c[0]), "+f"(c[1]), "+f"(c[2]), "+f"(c[3])
                 : "r"(a[0]), "r"(a[1]), "r"(a[2]), "r"(a[3]), "r"(b0), "r"(b1));
}
__device__ __forceinline__ uint32_t packbf2(bf16 a, bf16 b) {
    __nv_bfloat162 t = __halves2bfloat162(a, b);
    return *(uint32_t*)&t;
}
__device__ __forceinline__ uint32_t packsplit(float a, float b, uint32_t& lo) {
    bf16 ha = __float2bfloat16(a), hb = __float2bfloat16(b);
    bf16 la = __float2bfloat16(a - __bfloat162float(ha));
    bf16 lb = __float2bfloat16(b - __bfloat162float(hb));
    lo = packbf2(la, lb);
    return packbf2(ha, hb);
}

// ---------------- Elementwise fp32 -> bf16 hi/lo split ----------------
__global__ __launch_bounds__(256) void convert_split_kernel(
    const float* __restrict__ in, bf16* __restrict__ h, bf16* __restrict__ l, int n4)
{
    int i = blockIdx.x * 256 + threadIdx.x;
    if (i >= n4) return;
    float4 v = ((const float4*)in)[i];
    bf16 h0, h1, h2, h3, l0, l1, l2, l3;
    bsplit(v.x, h0, l0); bsplit(v.y, h1, l1); bsplit(v.z, h2, l2); bsplit(v.w, h3, l3);
    ((__nv_bfloat162*)h)[i * 2 + 0] = __halves2bfloat162(h0, h1);
    ((__nv_bfloat162*)h)[i * 2 + 1] = __halves2bfloat162(h2, h3);
    ((__nv_bfloat162*)l)[i * 2 + 0] = __halves2bfloat162(l0, l1);
    ((__nv_bfloat162*)l)[i * 2 + 1] = __halves2bfloat162(l2, l3);
}

// ---------------- Transposed fp32 [R,C] -> bf16 hi/lo [C,R] ----------------
__global__ void transpose_split_kernel(const float* __restrict__ src, int R, int C,
                                       bf16* __restrict__ h, bf16* __restrict__ l)
{
    __shared__ float t[32][33];
    int c0 = blockIdx.x * 32, r0 = blockIdx.y * 32;
    int tx = threadIdx.x, ty = threadIdx.y;
#pragma unroll
    for (int i = 0; i < 4; i++)
        t[ty + i * 8][tx] = src[(size_t)(r0 + ty + i * 8) * C + c0 + tx];
    __syncthreads();
#pragma unroll
    for (int i = 0; i < 4; i++) {
        int orow = c0 + ty + i * 8, oc = r0 + tx;
        bf16 hh, ll; bsplit(t[tx][ty + i * 8], hh, ll);
        h[(size_t)orow * R + oc] = hh;
        l[(size_t)orow * R + oc] = ll;
    }
}

// ---------------- ckv [b*2048+s][128] -> ckvT [b][c][s] bf16 hi/lo ----------------
__global__ void ckvt_split_kernel()
{
    __shared__ float t[32][33];
    int c0 = blockIdx.x * 32, s0 = blockIdx.y * 32, b = blockIdx.z;
    int tx = threadIdx.x, ty = threadIdx.y;
#pragma unroll
    for (int i = 0; i < 4; i++)
        t[ty + i * 8][tx] = g_ckv[(size_t)(b * SEQ + s0 + ty + i * 8) * KVC + c0 + tx];
    __syncthreads();
#pragma unroll
    for (int i = 0; i < 4; i++) {
        int c = c0 + ty + i * 8, s = s0 + tx;
        bf16 hh, ll; bsplit(t[tx][ty + i * 8], hh, ll);
        size_t o = ((size_t)b * KVC + c) * SEQ + s;
        g_ckvTh[o] = hh; g_ckvTl[o] = ll;
    }
}

// ---------------- RMSNorm (128 cols) -> bf16 hi/lo (+ optional fp32) ----------------
__global__ void rmsnorm_split_kernel(const float* __restrict__ in, int stride,
                                     const float* __restrict__ w,
                                     bf16* __restrict__ h, bf16* __restrict__ l,
                                     float* __restrict__ fout)
{
    __shared__ float red[128];
    const int row = blockIdx.x, c = threadIdx.x;
    float v = in[(size_t)row * stride + c];
    red[c] = v * v;
    __syncthreads();
#pragma unroll
    for (int o = 64; o > 0; o >>= 1) { if (c < o) red[c] += red[c + o]; __syncthreads(); }
    float r = w[c] * v * rsqrtf(red[0] * (1.f / 128.f) + EPSV);
    bf16 hh, ll; bsplit(r, hh, ll);
    h[(size_t)row * 128 + c] = hh;
    l[(size_t)row * 128 + c] = ll;
    if (fout) fout[(size_t)row * 128 + c] = r;
}

// ---------------- Assemble Q (nope + rope, pre-scaled) -> bf16 hi/lo ----------------
__global__ void assemble_q_kernel(const int* __restrict__ pos)
{
    const int s = blockIdx.x, bh = blockIdx.y;
    const int b = bh >> 3, h = bh & 7, c = threadIdx.x;
    const float* qrow = g_q + (size_t)(b * SEQ + s) * (NH * DQK);
    float v;
    if (c < QNOPE) v = qrow[h * QNOPE + c];
    else {
        int rc = c - QNOPE, i = rc >> 1;
        const float* rr = qrow + NH * QNOPE + h * QROPE;
        float xe = rr[2 * i], xo = rr[2 * i + 1];
        float p = (float)pos[b * SEQ + s];
        float ang = p * powf(10000.0f, -(2.0f * (float)i) / (float)QROPE);
        float cs = cosf(ang), sn = sinf(ang);
        v = (rc & 1) ? (xe * sn + xo * cs) : (xe * cs - xo * sn);
    }
    v *= SOFTMAX_SCALE;
    size_t o = ((size_t)bh * SEQ + s) * DQK + c;
    bf16 hh, ll; bsplit(v, hh, ll);
    g_Qh[o] = hh; g_Ql[o] = ll;
}

// ---------------- Assemble K -> bf16 hi/lo [bh][s][128] ----------------
__global__ void assemble_k_kernel(const int* __restrict__ pos)
{
    const int s = blockIdx.x, b = blockIdx.y, c = threadIdx.x;
    if (c < KNOPE) {
        const float* kvrow = g_kv + (size_t)(b * SEQ + s) * (NH * KNOPE);
#pragma unroll
        for (int h = 0; h < NH; h++) {
            float x = kvrow[h * KNOPE + c];
            size_t o = ((size_t)(b * NH + h) * SEQ + s) * DQK + c;
            bf16 hh, ll; bsplit(x, hh, ll);
            g_Kh[o] = hh; g_Kl[o] = ll;
        }
        return;
    }
    int rc = c - KNOPE, i = rc >> 1;
    const float* kr = g_comb + (size_t)(b * SEQ + s) * NCOMB + 256;
    float xe = kr[2 * i], xo = kr[2 * i + 1];
    float p = (float)pos[b * SEQ + s];
    float ang = p * powf(10000.0f, -(2.0f * (float)i) / (float)KROPE);
    float cs = cosf(ang), sn = sinf(ang);
    float v = (rc & 1) ? (xe * sn + xo * cs) : (xe * cs - xo * sn);
    bf16 hh, ll; bsplit(v, hh, ll);
#pragma unroll
    for (int h = 0; h < NH; h++) {
        size_t o = ((size_t)(b * NH + h) * SEQ + s) * DQK + c;
        g_Kh[o] = hh; g_Kl[o] = ll;
    }
}

// ---------------- Softmax over 2048 cols (S in bf16 hi/lo) -> bf16 hi/lo P ----------------
__global__ __launch_bounds__(256) void softmax_split_kernel()
{
    __shared__ float sred[8], sred2[8];
    size_t r = blockIdx.x;
    const uint4* rowh = (const uint4*)(g_Sh + r * SEQ);   // 8 bf16 per uint4
    const uint4* rowl = (const uint4*)(g_Sl + r * SEQ);
    int t = threadIdx.x, lane = t & 31, w = t >> 5;
    uint4 hv = rowh[t], lv = rowl[t];
    float e[8];
    {
        const __nv_bfloat162* hp = (const __nv_bfloat162*)&hv;
        const __nv_bfloat162* lp = (const __nv_bfloat162*)&lv;
#pragma unroll
        for (int i = 0; i < 4; i++) {
            float2 hf = __bfloat1622float2(hp[i]);
            float2 lf = __bfloat1622float2(lp[i]);
            e[2 * i] = hf.x + lf.x;
            e[2 * i + 1] = hf.y + lf.y;
        }
    }
    float mx = e[0];
#pragma unroll
    for (int i = 1; i < 8; i++) mx = fmaxf(mx, e[i]);
#pragma unroll
    for (int o = 16; o >= 1; o >>= 1) mx = fmaxf(mx, __shfl_xor_sync(0xffffffffu, mx, o));
    if (lane == 0) sred[w] = mx;
    __syncthreads();
    float mall = sred[0];
#pragma unroll
    for (int i = 1; i < 8; i++) mall = fmaxf(mall, sred[i]);
    float s = 0.f;
#pragma unroll
    for (int i = 0; i < 8; i++) { e[i] = __expf(e[i] - mall); s += e[i]; }
#pragma unroll
    for (int o = 16; o >= 1; o >>= 1) s += __shfl_xor_sync(0xffffffffu, s, o);
    if (lane == 0) sred2[w] = s;
    __syncthreads();
    float tot = sred2[0];
#pragma unroll
    for (int i = 1; i < 8; i++) tot += sred2[i];
    float inv = 1.f / tot;
    uint4 oh, ol;
    uint32_t* ohp = (uint32_t*)&oh;
    uint32_t* olp = (uint32_t*)&ol;
#pragma unroll
    for (int i = 0; i < 4; i++)
        ohp[i] = packsplit(e[2 * i] * inv, e[2 * i + 1] * inv, olp[i]);
    ((uint4*)(g_Ph + r * SEQ))[t] = oh;
    ((uint4*)(g_Pl + r * SEQ))[t] = ol;
}

// ---------------- bias_eff = w_o_b + b_v @ W_o  (one block per n) ----------------
__global__ __launch_bounds__(128) void bias_eff_kernel(
    const float* __restrict__ wo, const float* __restrict__ wo_b,
    const float* __restrict__ ukv_b)
{
    __shared__ float red[128];
    int n = blockIdx.x, t = threadIdx.x;
    float s = 0.f;
    for (int m = t; m < NH * VHD; m += 128)
        s += ukv_b[NH * KNOPE + m] * wo[(size_t)m * DIM + n];
    red[t] = s;
    __syncthreads();
#pragma unroll
    for (int o = 64; o > 0; o >>= 1) { if (t < o) red[t] += red[t + o]; __syncthreads(); }
    if (t == 0) g_bias_eff[n] = red[0] + wo_b[n];
}

// ---------------- concat biases [dq | dkv] ----------------
__global__ void combine_bias_kernel(const float* __restrict__ bdq, const float* __restrict__ bdkv)
{
    int i = threadIdx.x;                 // 0..319
    g_bcomb[i] = (i < QC) ? bdq[i] : bdkv[i - QC];
}

// ---------------- mma.sync bf16x3 GEMM (R11 2-stage mainloop) ----------------
// C[M,N] = scale * (A @ B^T) + bias.  A=[M,K] hi/lo lda, B=[N,K] hi/lo ldb (K-major).
// Block 128x64, BK=32, 8 warps (warp tile 32x32), cp.async double buffer.
// If outH != null, epilogue writes bf16 hi/lo instead of fp32 C.
#define AST 80
#define STAGE_B 30720
#define GEMM_SMEM (2 * STAGE_B)

__global__ __launch_bounds__(256, 2) void mma_gemm_kernel(
    const bf16* __restrict__ Ah, const bf16* __restrict__ Al,
    const bf16* __restrict__ Bh, const bf16* __restrict__ Bl,
    const float* __restrict__ bias, float* __restrict__ C,
    bf16* __restrict__ outH, bf16* __restrict__ outL,
    int K, int lda, int ldb, int ldc,
    long long sAb, long long sAh, long long sBb, long long sBh,
    long long sCb, long long sCh, float scale)
{
    extern __shared__ char smem[];
    uint32_t sb = smem_u32(smem);
    const int tid = threadIdx.x;
    const int wid = tid >> 5, lane = tid & 31;
    const int wr = wid >> 1, wc = wid & 1;
    const int bm = blockIdx.y * 128, bn = blockIdx.x * 64;
    const int z = blockIdx.z, zb = z >> 3, zh = z & 7;
    Ah += zb * sAb + zh * sAh; Al += zb * sAb + zh * sAh;
    Bh += zb * sBb + zh * sBh; Bl += zb * sBb + zh * sBh;
    const long long coff = zb * sCb + zh * sCh;

    const int NC = K >> 5;

    auto load_stage = [&](int c, int s) {
        uint32_t base = sb + s * STAGE_B;
        int k0 = c << 5;
#pragma unroll
        for (int t = 0; t < 2; t++) {
            int idx = tid + t * 256;
            int row = idx >> 2, ch = idx & 3;
            size_t go = (size_t)(bm + row) * lda + k0 + ch * 8;
            uint32_t so = base + row * AST + ch * 16;
            cp16(so, Ah + go);
            cp16(so + 10240, Al + go);
        }
        {
            int row = tid >> 2, ch = tid & 3;
            size_t go = (size_t)(bn + row) * ldb + k0 + ch * 8;
            uint32_t so = base + 20480 + row * AST + ch * 16;
            cp16(so, Bh + go);
            cp16(so + 5120, Bl + go);
        }
        CP_COMMIT();
    };

    float acc[2][4][4];
#pragma unroll
    for (int i = 0; i < 2; i++)
#pragma unroll
        for (int j = 0; j < 4; j++)
#pragma unroll
            for (int q = 0; q < 4; q++) acc[i][j][q] = 0.f;

    load_stage(0, 0);

    for (int c = 0; c < NC; c++) {
        if (c + 1 < NC) { load_stage(c + 1, (c + 1) & 1); CP_WAIT1(); }
        else CP_WAIT0();
        __syncthreads();

        uint32_t base = sb + (c & 1) * STAGE_B;
#pragma unroll
        for (int kk = 0; kk < 2; kk++) {
            int ch = kk * 2 + (lane >> 4);
            uint32_t ah[2][4], al[2][4], bh[2][4], bl[2][4];
#pragma unroll
            for (int mi = 0; mi < 2; mi++) {
                int r = wr * 32 + mi * 16 + (lane & 15);
                uint32_t ad = base + r * AST + ch * 16;
                lds4(ad, ah[mi]);
                lds4(ad + 10240, al[mi]);
            }
#pragma unroll
            for (int ni = 0; ni < 2; ni++) {
                int r = wc * 32 + ni * 16 + (lane & 15);
                uint32_t bd = base + 20480 + r * AST + ch * 16;
                lds4(bd, bh[ni]);
                lds4(bd + 5120, bl[ni]);
            }
#pragma unroll
            for (int mi = 0; mi < 2; mi++)
#pragma unroll
                for (int ni = 0; ni < 2; ni++)
#pragma unroll
                    for (int sub = 0; sub < 2; sub++) {
                        int nj = ni * 2 + sub;
                        mma16816(acc[mi][nj], ah[mi], bh[ni][sub], bh[ni][sub + 2]);
                        mma16816(acc[mi][nj], ah[mi], bl[ni][sub], bl[ni][sub + 2]);
                        mma16816(acc[mi][nj], al[mi], bh[ni][sub], bh[ni][sub + 2]);
                    }
        }
        __syncthreads();
    }

    const int g = lane >> 2, q = lane & 3;
#pragma unroll
    for (int mi = 0; mi < 2; mi++) {
#pragma unroll
        for (int nj = 0; nj < 4; nj++) {
            int col = bn + wc * 32 + nj * 8 + q * 2;
            float bx = 0.f, by = 0.f;
            if (bias) { bx = bias[col]; by = bias[col + 1]; }
            int r0 = bm + wr * 32 + mi * 16 + g;
            float v00 = acc[mi][nj][0] * scale + bx;
            float v01 = acc[mi][nj][1] * scale + by;
            float v10 = acc[mi][nj][2] * scale + bx;
            float v11 = acc[mi][nj][3] * scale + by;
            if (outH) {
                size_t o0 = coff + (size_t)r0 * ldc + col;
                size_t o1 = coff + (size_t)(r0 + 8) * ldc + col;
                uint32_t lo0, hi0 = packsplit(v00, v01, lo0);
                uint32_t lo1, hi1 = packsplit(v10, v11, lo1);
                *(uint32_t*)(outH + o0) = hi0; *(uint32_t*)(outL + o0) = lo0;
                *(uint32_t*)(outH + o1) = hi1; *(uint32_t*)(outL + o1) = lo1;
            } else {
                float* Cp = C + coff;
                float2 o0 = {v00, v01}, o1 = {v10, v11};
                *(float2*)&Cp[(size_t)r0 * ldc + col] = o0;
                *(float2*)&Cp[(size_t)(r0 + 8) * ldc + col] = o1;
            }
        }
    }
}

// ---------------- Launch ----------------
static void run_gemm(const bf16* Ah, const bf16* Al, const bf16* Bh, const bf16* Bl,
                     const float* bias, float* C, bf16* outH, bf16* outL,
                     int M, int N, int K, int batches,
                     int lda, int ldb, int ldc,
                     long long sAb, long long sAh, long long sBb, long long sBh,
                     long long sCb, long long sCh, float scale)
{
    mma_gemm_kernel<<<dim3(N / 64, M / 128, batches), 256, GEMM_SMEM>>>(
        Ah, Al, Bh, Bl, bias, C, outH, outL, K, lda, ldb, ldc,
        sAb, sAh, sBb, sBh, sCb, sCh, scale);
}

extern "C" void kernel_launch(void* const* d_in, const int* in_sizes, int n_in,
                              void* d_out, int out_size)
{
    const float* x        = (const float*)d_in[0];
    const int*   pos      = (const int*)d_in[1];
    const float* w_dq_w   = (const float*)d_in[2];
    const float* w_dq_b   = (const float*)d_in[3];
    const float* q_norm_w = (const float*)d_in[4];
    const float* w_uq_w   = (const float*)d_in[5];
    const float* w_uq_b   = (const float*)d_in[6];
    const float* w_dkv_w  = (const float*)d_in[7];
    const float* w_dkv_b  = (const float*)d_in[8];
    const float* kv_norm_w= (const float*)d_in[9];
    const float* w_ukv_w  = (const float*)d_in[10];
    const float* w_ukv_b  = (const float*)d_in[11];
    const float* w_o_w    = (const float*)d_in[12];
    const float* w_o_b    = (const float*)d_in[13];
    float* out = (float*)d_out;

    cudaFuncSetAttribute(mma_gemm_kernel, cudaFuncAttributeMaxDynamicSharedMemorySize, GEMM_SMEM);

    float *comb, *q, *ckv, *kv, *Wf, *beff, *bcomb;
    bf16 *Sh, *Sl;
    bf16 *xh, *xl, *cqh, *cql, *ckvh, *ckvl, *ckvTh, *ckvTl, *Qh, *Ql, *Kh, *Kl, *Ph, *Pl;
    bf16 *ctxh, *ctxl, *wcombh, *wcombl, *wuqh, *wuql;
    bf16 *wukvh, *wukvl, *wukvnth, *wukvntl, *woh, *wol, *WfBh, *WfBl;
    cudaGetSymbolAddress((void**)&comb, g_comb);   cudaGetSymbolAddress((void**)&q, g_q);
    cudaGetSymbolAddress((void**)&ckv, g_ckv);     cudaGetSymbolAddress((void**)&kv, g_kv);
    cudaGetSymbolAddress((void**)&Sh, g_Sh);       cudaGetSymbolAddress((void**)&Sl, g_Sl);
    cudaGetSymbolAddress((void**)&Wf, g_Wf);
    cudaGetSymbolAddress((void**)&beff, g_bias_eff); cudaGetSymbolAddress((void**)&bcomb, g_bcomb);
    cudaGetSymbolAddress((void**)&xh, g_xh);       cudaGetSymbolAddress((void**)&xl, g_xl);
    cudaGetSymbolAddress((void**)&cqh, g_cqh);     cudaGetSymbolAddress((void**)&cql, g_cql);
    cudaGetSymbolAddress((void**)&ckvh, g_ckvh);   cudaGetSymbolAddress((void**)&ckvl, g_ckvl);
    cudaGetSymbolAddress((void**)&ckvTh, g_ckvTh); cudaGetSymbolAddress((void**)&ckvTl, g_ckvTl);
    cudaGetSymbolAddress((void**)&Qh, g_Qh);       cudaGetSymbolAddress((void**)&Ql, g_Ql);
    cudaGetSymbolAddress((void**)&Kh, g_Kh);       cudaGetSymbolAddress((void**)&Kl, g_Kl);
    cudaGetSymbolAddress((void**)&Ph, g_Ph);       cudaGetSymbolAddress((void**)&Pl, g_Pl);
    cudaGetSymbolAddress((void**)&ctxh, g_ctxh);   cudaGetSymbolAddress((void**)&ctxl, g_ctxl);
    cudaGetSymbolAddress((void**)&wcombh, g_wcombh); cudaGetSymbolAddress((void**)&wcombl, g_wcombl);
    cudaGetSymbolAddress((void**)&wuqh, g_wuqh);   cudaGetSymbolAddress((void**)&wuql, g_wuql);
    cudaGetSymbolAddress((void**)&wukvh, g_wukvh); cudaGetSymbolAddress((void**)&wukvl, g_wukvl);
    cudaGetSymbolAddress((void**)&wukvnth, g_wukvnth); cudaGetSymbolAddress((void**)&wukvntl, g_wukvntl);
    cudaGetSymbolAddress((void**)&woh, g_woh);     cudaGetSymbolAddress((void**)&wol, g_wol);
    cudaGetSymbolAddress((void**)&WfBh, g_WfBh);   cudaGetSymbolAddress((void**)&WfBl, g_WfBl);

    // ---- Operand conversions ----
    convert_split_kernel<<<(BS * DIM / 4) / 256, 256>>>(x, xh, xl, BS * DIM / 4);
    convert_split_kernel<<<(KVC * 2560 / 4 + 255) / 256, 256>>>(w_ukv_w, wukvnth, wukvntl, KVC * 2560 / 4);
    // combined projection weight: rows 0-127 = w_dq^T, rows 128-319 = w_dkv^T
    transpose_split_kernel<<<dim3(QC / 32, DIM / 32), dim3(32, 8)>>>(w_dq_w, DIM, QC, wcombh, wcombl);
    transpose_split_kernel<<<dim3((KVC + KROPE) / 32, DIM / 32), dim3(32, 8)>>>(
        w_dkv_w, DIM, KVC + KROPE, wcombh + (size_t)QC * DIM, wcombl + (size_t)QC * DIM);
    transpose_split_kernel<<<dim3((NH * DQK) / 32, QC / 32), dim3(32, 8)>>>(w_uq_w, QC, NH * DQK, wuqh, wuql);
    transpose_split_kernel<<<dim3((NH * KNOPE) / 32, KVC / 32), dim3(32, 8)>>>(w_ukv_w, KVC, NH * (KNOPE + VHD), wukvh, wukvl);
    transpose_split_kernel<<<dim3(DIM / 32, (NH * VHD) / 32), dim3(32, 8)>>>(w_o_w, NH * VHD, DIM, woh, wol);
    combine_bias_kernel<<<1, NCOMB>>>(w_dq_b, w_dkv_b);

    // ---- W_f = W_uv_h @ W_o_h  (batched over h), transpose to B layout ----
    run_gemm(wukvnth + NH * KNOPE, wukvntl + NH * KNOPE, woh, wol, nullptr, Wf, nullptr, nullptr,
             KVC, DIM, VHD, NH,
             NH * (KNOPE + VHD), NH * VHD, DIM,
             0, VHD, 0, VHD,
             0, (long long)KVC * DIM, 1.f);
    transpose_split_kernel<<<dim3(DIM / 32, DIM / 32), dim3(32, 8)>>>(Wf, DIM, DIM, WfBh, WfBl);
    bias_eff_kernel<<<DIM, 128>>>(w_o_w, w_o_b, w_ukv_b);

    // 1) comb = x @ [w_dq | w_dkv] + b     (N=320)
    run_gemm(xh, xl, wcombh, wcombl, bcomb, comb, nullptr, nullptr, BS, NCOMB, DIM, 1,
             DIM, DIM, NCOMB, 0, 0, 0, 0, 0, 0, 1.f);
    // 2) cq = rmsnorm(comb[:, :128]) -> hi/lo
    rmsnorm_split_kernel<<<BS, 128>>>(comb, NCOMB, q_norm_w, cqh, cql, nullptr);
    // 3) ckv = rmsnorm(comb[:, 128:256]) -> hi/lo + fp32
    rmsnorm_split_kernel<<<BS, 128>>>(comb + KVC, NCOMB, kv_norm_w, ckvh, ckvl, ckv);
    // 3b) ckvT for ctx GEMM
    ckvt_split_kernel<<<dim3(KVC / 32, SEQ / 32, BATCH), dim3(32, 8)>>>();
    // 4) q = cq @ w_uq + b
    run_gemm(cqh, cql, wuqh, wuql, w_uq_b, q, nullptr, nullptr, BS, NH * DQK, QC, 1,
             QC, QC, NH * DQK, 0, 0, 0, 0, 0, 0, 1.f);
    // 5) k_nope = ckv @ w_uk + b  (N=512)
    run_gemm(ckvh, ckvl, wukvh, wukvl, w_ukv_b, kv, nullptr, nullptr, BS, NH * KNOPE, KVC, 1,
             KVC, KVC, NH * KNOPE, 0, 0, 0, 0, 0, 0, 1.f);
    // 6-7) assemble Q (scaled, rope) / K (rope)
    assemble_q_kernel<<<dim3(SEQ, BATCH * NH), 128>>>(pos);
    assemble_k_kernel<<<dim3(SEQ, BATCH), 128>>>(pos);
    // 8) S = Q @ K^T -> bf16 hi/lo directly (halves S traffic)
    run_gemm(Qh, Ql, Kh, Kl, nullptr, nullptr, Sh, Sl, SEQ, SEQ, DQK, BATCH * NH,
             DQK, DQK, SEQ,
             8LL * SEQ * DQK, (long long)SEQ * DQK,
             8LL * SEQ * DQK, (long long)SEQ * DQK,
             8LL * SEQ * SEQ, (long long)SEQ * SEQ, 1.f);
    // 9) P = softmax(S) -> hi/lo
    softmax_split_kernel<<<16 * SEQ, 256>>>();
    // 10) ctx = P @ ckv -> bf16 hi/lo directly
    run_gemm(Ph, Pl, ckvTh, ckvTl, nullptr, nullptr, ctxh, ctxl, SEQ, KVC, SEQ, BATCH * NH,
             SEQ, SEQ, NH * KVC,
             8LL * SEQ * SEQ, (long long)SEQ * SEQ,
             (long long)KVC * SEQ, 0,
             (long long)SEQ * NH * KVC, KVC, 1.f);
    // 11) out = ctx @ W_f + bias_eff
    run_gemm(ctxh, ctxl, WfBh, WfBl, beff, out, nullptr, nullptr, BS, DIM, NH * KVC, 1,
             NH * KVC, NH * KVC, DIM, 0, 0, 0, 0, 0, 0, 1.f);
}

// round 15
// speedup vs baseline: 1.0952x; 1.0952x over previous
#include <cuda_runtime.h>
#include <cuda_bf16.h>
#include <cstdint>
#include <math.h>

typedef __nv_bfloat16 bf16;

// ---------------- Problem constants ----------------
#define BATCH 2
#define SEQ 2048
#define BS 4096
#define DIM 1024
#define NH 8
#define QC 128
#define QNOPE 96
#define QROPE 32
#define KVC 128
#define KNOPE 64
#define KROPE 64
#define VHD 256
#define DQK 128
#define NCOMB 320                      // QC + KVC + KROPE
#define EPSV 1e-8f
#define SOFTMAX_SCALE 0.08838834764831845f

// ---------------- Scratch (device globals) ----------------
__device__ float g_comb[BS * NCOMB];               // [dq(128) | ckv(128) | krope(64)]
__device__ float g_ckv[BS * KVC];
__device__ float g_S[16 * SEQ * SEQ];              // 256 MB scores (fp32 — R13 proven)
__device__ float g_Wf[DIM * DIM];
__device__ float g_bias_eff[DIM];
__device__ float g_bcomb[NCOMB];

__device__ bf16 g_xh[BS * DIM],  g_xl[BS * DIM];
__device__ bf16 g_cqh[BS * QC],  g_cql[BS * QC];
__device__ bf16 g_ckvh[BS * KVC], g_ckvl[BS * KVC];
__device__ bf16 g_ckvTh[BATCH * KVC * SEQ], g_ckvTl[BATCH * KVC * SEQ];
__device__ bf16 g_Qh[BATCH * NH * SEQ * DQK], g_Ql[BATCH * NH * SEQ * DQK];
__device__ bf16 g_Kh[BATCH * NH * SEQ * DQK], g_Kl[BATCH * NH * SEQ * DQK];
__device__ bf16 g_Ph[16 * SEQ * SEQ], g_Pl[16 * SEQ * SEQ];
__device__ bf16 g_ctxh[BS * NH * KVC], g_ctxl[BS * NH * KVC];
__device__ bf16 g_wcombh[NCOMB * DIM], g_wcombl[NCOMB * DIM];   // transposed dq|dkv
__device__ bf16 g_wuqh[NH * DQK * QC], g_wuql[NH * DQK * QC];
__device__ bf16 g_wukvh[(NH * KNOPE) * KVC], g_wukvl[(NH * KNOPE) * KVC];
__device__ bf16 g_wukvnth[KVC * (NH * (KNOPE + VHD))], g_wukvntl[KVC * (NH * (KNOPE + VHD))];
__device__ bf16 g_woh[DIM * NH * VHD], g_wol[DIM * NH * VHD];
__device__ bf16 g_WfBh[DIM * DIM], g_WfBl[DIM * DIM];

__device__ __forceinline__ void bsplit(float x, bf16& h, bf16& l) {
    h = __float2bfloat16(x);
    l = __float2bfloat16(x - __bfloat162float(h));
}
__device__ __forceinline__ uint32_t smem_u32(const void* p) {
    uint32_t a;
    asm("{ .reg .u64 t; cvta.to.shared.u64 t, %1; cvt.u32.u64 %0, t; }" : "=r"(a) : "l"(p));
    return a;
}
__device__ __forceinline__ void cp16(uint32_t s, const void* g) {
    asm volatile("cp.async.ca.shared.global [%0], [%1], 16;" :: "r"(s), "l"(g));
}
#define CP_COMMIT() asm volatile("cp.async.commit_group;" ::: "memory")
#define CP_WAIT0()  asm volatile("cp.async.wait_group 0;" ::: "memory")
#define CP_WAIT1()  asm volatile("cp.async.wait_group 1;" ::: "memory")

__device__ __forceinline__ void lds4(uint32_t addr, uint32_t* r) {
    asm volatile("ldmatrix.sync.aligned.m8n8.x4.shared.b16 {%0,%1,%2,%3}, [%4];"
                 : "=r"(r[0]), "=r"(r[1]), "=r"(r[2]), "=r"(r[3]) : "r"(addr));
}
__device__ __forceinline__ void mma16816(float* c, const uint32_t* a, uint32_t b0, uint32_t b1) {
    asm volatile("mma.sync.aligned.m16n8k16.row.col.f32.bf16.bf16.f32 "
                 "{%0,%1,%2,%3}, {%4,%5,%6,%7}, {%8,%9}, {%0,%1,%2,%3};"
                 : "+f"(c[0]), "+f"(c[1]), "+f"(c[2]), "+f"(c[3])
                 : "r"(a[0]), "r"(a[1]), "r"(a[2]), "r"(a[3]), "r"(b0), "r"(b1));
}
__device__ __forceinline__ uint32_t packbf2(bf16 a, bf16 b) {
    __nv_bfloat162 t = __halves2bfloat162(a, b);
    return *(uint32_t*)&t;
}
__device__ __forceinline__ uint32_t packsplit(float a, float b, uint32_t& lo) {
    bf16 ha = __float2bfloat16(a), hb = __float2bfloat16(b);
    bf16 la = __float2bfloat16(a - __bfloat162float(ha));
    bf16 lb = __float2bfloat16(b - __bfloat162float(hb));
    lo = packbf2(la, lb);
    return packbf2(ha, hb);
}

// ---------------- Elementwise fp32 -> bf16 hi/lo split ----------------
__global__ __launch_bounds__(256) void convert_split_kernel(
    const float* __restrict__ in, bf16* __restrict__ h, bf16* __restrict__ l, int n4)
{
    int i = blockIdx.x * 256 + threadIdx.x;
    if (i >= n4) return;
    float4 v = ((const float4*)in)[i];
    bf16 h0, h1, h2, h3, l0, l1, l2, l3;
    bsplit(v.x, h0, l0); bsplit(v.y, h1, l1); bsplit(v.z, h2, l2); bsplit(v.w, h3, l3);
    ((__nv_bfloat162*)h)[i * 2 + 0] = __halves2bfloat162(h0, h1);
    ((__nv_bfloat162*)h)[i * 2 + 1] = __halves2bfloat162(h2, h3);
    ((__nv_bfloat162*)l)[i * 2 + 0] = __halves2bfloat162(l0, l1);
    ((__nv_bfloat162*)l)[i * 2 + 1] = __halves2bfloat162(l2, l3);
}

// ---------------- Transposed fp32 [R,C] -> bf16 hi/lo [C,R] ----------------
__global__ void transpose_split_kernel(const float* __restrict__ src, int R, int C,
                                       bf16* __restrict__ h, bf16* __restrict__ l)
{
    __shared__ float t[32][33];
    int c0 = blockIdx.x * 32, r0 = blockIdx.y * 32;
    int tx = threadIdx.x, ty = threadIdx.y;
#pragma unroll
    for (int i = 0; i < 4; i++)
        t[ty + i * 8][tx] = src[(size_t)(r0 + ty + i * 8) * C + c0 + tx];
    __syncthreads();
#pragma unroll
    for (int i = 0; i < 4; i++) {
        int orow = c0 + ty + i * 8, oc = r0 + tx;
        bf16 hh, ll; bsplit(t[tx][ty + i * 8], hh, ll);
        h[(size_t)orow * R + oc] = hh;
        l[(size_t)orow * R + oc] = ll;
    }
}

// ---------------- ckv [b*2048+s][128] -> ckvT [b][c][s] bf16 hi/lo ----------------
__global__ void ckvt_split_kernel()
{
    __shared__ float t[32][33];
    int c0 = blockIdx.x * 32, s0 = blockIdx.y * 32, b = blockIdx.z;
    int tx = threadIdx.x, ty = threadIdx.y;
#pragma unroll
    for (int i = 0; i < 4; i++)
        t[ty + i * 8][tx] = g_ckv[(size_t)(b * SEQ + s0 + ty + i * 8) * KVC + c0 + tx];
    __syncthreads();
#pragma unroll
    for (int i = 0; i < 4; i++) {
        int c = c0 + ty + i * 8, s = s0 + tx;
        bf16 hh, ll; bsplit(t[tx][ty + i * 8], hh, ll);
        size_t o = ((size_t)b * KVC + c) * SEQ + s;
        g_ckvTh[o] = hh; g_ckvTl[o] = ll;
    }
}

// ---------------- RMSNorm (128 cols) -> bf16 hi/lo (+ optional fp32) ----------------
__global__ void rmsnorm_split_kernel(const float* __restrict__ in, int stride,
                                     const float* __restrict__ w,
                                     bf16* __restrict__ h, bf16* __restrict__ l,
                                     float* __restrict__ fout)
{
    __shared__ float red[128];
    const int row = blockIdx.x, c = threadIdx.x;
    float v = in[(size_t)row * stride + c];
    red[c] = v * v;
    __syncthreads();
#pragma unroll
    for (int o = 64; o > 0; o >>= 1) { if (c < o) red[c] += red[c + o]; __syncthreads(); }
    float r = w[c] * v * rsqrtf(red[0] * (1.f / 128.f) + EPSV);
    bf16 hh, ll; bsplit(r, hh, ll);
    h[(size_t)row * 128 + c] = hh;
    l[(size_t)row * 128 + c] = ll;
    if (fout) fout[(size_t)row * 128 + c] = r;
}

// ---------------- K rope (cols 64-127, broadcast to 8 heads) ----------------
__global__ void assemble_krope_kernel(const int* __restrict__ pos)
{
    const int s = blockIdx.x, b = blockIdx.y, rc = threadIdx.x;   // rc 0..63
    int i = rc >> 1;
    const float* kr = g_comb + (size_t)(b * SEQ + s) * NCOMB + 256;
    float xe = kr[2 * i], xo = kr[2 * i + 1];
    float p = (float)pos[b * SEQ + s];
    float ang = p * powf(10000.0f, -(2.0f * (float)i) / (float)KROPE);
    float cs = cosf(ang), sn = sinf(ang);
    float v = (rc & 1) ? (xe * sn + xo * cs) : (xe * cs - xo * sn);
    bf16 hh, ll; bsplit(v, hh, ll);
#pragma unroll
    for (int h = 0; h < NH; h++) {
        size_t o = ((size_t)(b * NH + h) * SEQ + s) * DQK + KNOPE + rc;
        g_Kh[o] = hh; g_Kl[o] = ll;
    }
}

// ---------------- Softmax over 2048 cols (fp32 S) -> bf16 hi/lo P ----------------
__global__ __launch_bounds__(256) void softmax_split_kernel()
{
    __shared__ float sred[8], sred2[8];
    size_t r = blockIdx.x;
    const float4* row = (const float4*)(g_S + r * SEQ);
    int t = threadIdx.x, lane = t & 31, w = t >> 5;
    float4 v0 = row[t], v1 = row[t + 256];
    float mx = fmaxf(fmaxf(fmaxf(v0.x, v0.y), fmaxf(v0.z, v0.w)),
                     fmaxf(fmaxf(v1.x, v1.y), fmaxf(v1.z, v1.w)));
#pragma unroll
    for (int o = 16; o >= 1; o >>= 1) mx = fmaxf(mx, __shfl_xor_sync(0xffffffffu, mx, o));
    if (lane == 0) sred[w] = mx;
    __syncthreads();
    float mall = sred[0];
#pragma unroll
    for (int i = 1; i < 8; i++) mall = fmaxf(mall, sred[i]);
    float e[8];
    e[0] = __expf(v0.x - mall); e[1] = __expf(v0.y - mall);
    e[2] = __expf(v0.z - mall); e[3] = __expf(v0.w - mall);
    e[4] = __expf(v1.x - mall); e[5] = __expf(v1.y - mall);
    e[6] = __expf(v1.z - mall); e[7] = __expf(v1.w - mall);
    float s = e[0] + e[1] + e[2] + e[3] + e[4] + e[5] + e[6] + e[7];
#pragma unroll
    for (int o = 16; o >= 1; o >>= 1) s += __shfl_xor_sync(0xffffffffu, s, o);
    if (lane == 0) sred2[w] = s;
    __syncthreads();
    float tot = sred2[0];
#pragma unroll
    for (int i = 1; i < 8; i++) tot += sred2[i];
    float inv = 1.f / tot;
    bf16 h[8], l[8];
#pragma unroll
    for (int i = 0; i < 8; i++) bsplit(e[i] * inv, h[i], l[i]);
    __nv_bfloat162* Ph2 = (__nv_bfloat162*)(g_Ph + r * SEQ);
    __nv_bfloat162* Pl2 = (__nv_bfloat162*)(g_Pl + r * SEQ);
    Ph2[t * 2 + 0] = __halves2bfloat162(h[0], h[1]);
    Ph2[t * 2 + 1] = __halves2bfloat162(h[2], h[3]);
    Ph2[512 + t * 2 + 0] = __halves2bfloat162(h[4], h[5]);
    Ph2[512 + t * 2 + 1] = __halves2bfloat162(h[6], h[7]);
    Pl2[t * 2 + 0] = __halves2bfloat162(l[0], l[1]);
    Pl2[t * 2 + 1] = __halves2bfloat162(l[2], l[3]);
    Pl2[512 + t * 2 + 0] = __halves2bfloat162(l[4], l[5]);
    Pl2[512 + t * 2 + 1] = __halves2bfloat162(l[6], l[7]);
}

// ---------------- bias_eff = w_o_b + b_v @ W_o  (one block per n) ----------------
__global__ __launch_bounds__(128) void bias_eff_kernel(
    const float* __restrict__ wo, const float* __restrict__ wo_b,
    const float* __restrict__ ukv_b)
{
    __shared__ float red[128];
    int n = blockIdx.x, t = threadIdx.x;
    float s = 0.f;
    for (int m = t; m < NH * VHD; m += 128)
        s += ukv_b[NH * KNOPE + m] * wo[(size_t)m * DIM + n];
    red[t] = s;
    __syncthreads();
#pragma unroll
    for (int o = 64; o > 0; o >>= 1) { if (t < o) red[t] += red[t + o]; __syncthreads(); }
    if (t == 0) g_bias_eff[n] = red[0] + wo_b[n];
}

// ---------------- concat biases [dq | dkv] ----------------
__global__ void combine_bias_kernel(const float* __restrict__ bdq, const float* __restrict__ bdkv)
{
    int i = threadIdx.x;                 // 0..319
    g_bcomb[i] = (i < QC) ? bdq[i] : bdkv[i - QC];
}

// ---------------- mma.sync bf16x3 GEMM (R11/R13 2-stage mainloop, modal epilogue) ----------------
// C[M,N] = scale * (A @ B^T) + bias.  A=[M,K] hi/lo lda, B=[N,K] hi/lo ldb (K-major).
// Block 128x64, BK=32, 8 warps (warp tile 32x32), cp.async double buffer.
// mode 0: fp32 C.  mode 1: bf16 hi/lo (outH/outL, ldc).
// mode 2: Q assembly — bias, rope on col-pairs, *SOFTMAX_SCALE, scatter to [bh][s][128].
// mode 3: K-nope assembly — bias, scatter cols 0-63 per head to [bh][s][128].
#define AST 80
#define STAGE_B 30720
#define GEMM_SMEM (2 * STAGE_B)

__global__ __launch_bounds__(256, 2) void mma_gemm_kernel(
    const bf16* __restrict__ Ah, const bf16* __restrict__ Al,
    const bf16* __restrict__ Bh, const bf16* __restrict__ Bl,
    const float* __restrict__ bias, float* __restrict__ C,
    bf16* __restrict__ outH, bf16* __restrict__ outL,
    const int* __restrict__ pos, int mode,
    int K, int lda, int ldb, int ldc,
    long long sAb, long long sAh, long long sBb, long long sBh,
    long long sCb, long long sCh, float scale)
{
    extern __shared__ char smem[];
    uint32_t sb = smem_u32(smem);
    const int tid = threadIdx.x;
    const int wid = tid >> 5, lane = tid & 31;
    const int wr = wid >> 1, wc = wid & 1;
    const int bm = blockIdx.y * 128, bn = blockIdx.x * 64;
    const int z = blockIdx.z, zb = z >> 3, zh = z & 7;
    Ah += zb * sAb + zh * sAh; Al += zb * sAb + zh * sAh;
    Bh += zb * sBb + zh * sBh; Bl += zb * sBb + zh * sBh;
    const long long coff = zb * sCb + zh * sCh;

    const int NC = K >> 5;

    auto load_stage = [&](int c, int s) {
        uint32_t base = sb + s * STAGE_B;
        int k0 = c << 5;
#pragma unroll
        for (int t = 0; t < 2; t++) {
            int idx = tid + t * 256;
            int row = idx >> 2, ch = idx & 3;
            size_t go = (size_t)(bm + row) * lda + k0 + ch * 8;
            uint32_t so = base + row * AST + ch * 16;
            cp16(so, Ah + go);
            cp16(so + 10240, Al + go);
        }
        {
            int row = tid >> 2, ch = tid & 3;
            size_t go = (size_t)(bn + row) * ldb + k0 + ch * 8;
            uint32_t so = base + 20480 + row * AST + ch * 16;
            cp16(so, Bh + go);
            cp16(so + 5120, Bl + go);
        }
        CP_COMMIT();
    };

    float acc[2][4][4];
#pragma unroll
    for (int i = 0; i < 2; i++)
#pragma unroll
        for (int j = 0; j < 4; j++)
#pragma unroll
            for (int q = 0; q < 4; q++) acc[i][j][q] = 0.f;

    load_stage(0, 0);

    for (int c = 0; c < NC; c++) {
        if (c + 1 < NC) { load_stage(c + 1, (c + 1) & 1); CP_WAIT1(); }
        else CP_WAIT0();
        __syncthreads();

        uint32_t base = sb + (c & 1) * STAGE_B;
#pragma unroll
        for (int kk = 0; kk < 2; kk++) {
            int ch = kk * 2 + (lane >> 4);
            uint32_t ah[2][4], al[2][4], bh[2][4], bl[2][4];
#pragma unroll
            for (int mi = 0; mi < 2; mi++) {
                int r = wr * 32 + mi * 16 + (lane & 15);
                uint32_t ad = base + r * AST + ch * 16;
                lds4(ad, ah[mi]);
                lds4(ad + 10240, al[mi]);
            }
#pragma unroll
            for (int ni = 0; ni < 2; ni++) {
                int r = wc * 32 + ni * 16 + (lane & 15);
                uint32_t bd = base + 20480 + r * AST + ch * 16;
                lds4(bd, bh[ni]);
                lds4(bd + 5120, bl[ni]);
            }
#pragma unroll
            for (int mi = 0; mi < 2; mi++)
#pragma unroll
                for (int ni = 0; ni < 2; ni++)
#pragma unroll
                    for (int sub = 0; sub < 2; sub++) {
                        int nj = ni * 2 + sub;
                        mma16816(acc[mi][nj], ah[mi], bh[ni][sub], bh[ni][sub + 2]);
                        mma16816(acc[mi][nj], ah[mi], bl[ni][sub], bl[ni][sub + 2]);
                        mma16816(acc[mi][nj], al[mi], bh[ni][sub], bh[ni][sub + 2]);
                    }
        }
        __syncthreads();
    }

    const int g = lane >> 2, q = lane & 3;
#pragma unroll
    for (int mi = 0; mi < 2; mi++) {
#pragma unroll
        for (int nj = 0; nj < 4; nj++) {
            int col = bn + wc * 32 + nj * 8 + q * 2;
            float bx = 0.f, by = 0.f;
            if (bias) { bx = bias[col]; by = bias[col + 1]; }
            int r0 = bm + wr * 32 + mi * 16 + g;
            float v00 = acc[mi][nj][0] * scale + bx;
            float v01 = acc[mi][nj][1] * scale + by;
            float v10 = acc[mi][nj][2] * scale + bx;
            float v11 = acc[mi][nj][3] * scale + by;
            if (mode == 0) {
                float* Cp = C + coff;
                float2 o0 = {v00, v01}, o1 = {v10, v11};
                *(float2*)&Cp[(size_t)r0 * ldc + col] = o0;
                *(float2*)&Cp[(size_t)(r0 + 8) * ldc + col] = o1;
            } else if (mode == 1) {
                size_t o0 = coff + (size_t)r0 * ldc + col;
                size_t o1 = coff + (size_t)(r0 + 8) * ldc + col;
                uint32_t lo0, hi0 = packsplit(v00, v01, lo0);
                uint32_t lo1, hi1 = packsplit(v10, v11, lo1);
                *(uint32_t*)(outH + o0) = hi0; *(uint32_t*)(outL + o0) = lo0;
                *(uint32_t*)(outH + o1) = hi1; *(uint32_t*)(outL + o1) = lo1;
            } else if (mode == 2) {
                // Q assembly: rope on rope-region pairs, scale, scatter
#pragma unroll
                for (int rr = 0; rr < 2; rr++) {
                    int r = r0 + rr * 8;
                    float va = rr ? v10 : v00, vb = rr ? v11 : v01;
                    int b = r >> 11, s = r & 2047;
                    int h, cc;
                    if (col < NH * QNOPE) { h = col / QNOPE; cc = col - h * QNOPE; }
                    else {
                        int rcc = col - NH * QNOPE;
                        h = rcc >> 5;
                        int rc = rcc & 31;
                        cc = QNOPE + rc;
                        int i = rc >> 1;
                        float p = (float)pos[r];
                        float ang = p * powf(10000.0f, -(2.0f * (float)i) / (float)QROPE);
                        float cs = cosf(ang), sn = sinf(ang);
                        float xe = va, xo = vb;
                        va = xe * cs - xo * sn;
                        vb = xe * sn + xo * cs;
                    }
                    va *= SOFTMAX_SCALE; vb *= SOFTMAX_SCALE;
                    size_t o = ((size_t)(b * NH + h) * SEQ + s) * DQK + cc;
                    uint32_t lo, hi = packsplit(va, vb, lo);
                    *(uint32_t*)(outH + o) = hi; *(uint32_t*)(outL + o) = lo;
                }
            } else {
                // K-nope assembly: scatter cols 0-63 per head
#pragma unroll
                for (int rr = 0; rr < 2; rr++) {
                    int r = r0 + rr * 8;
                    float va = rr ? v10 : v00, vb = rr ? v11 : v01;
                    int b = r >> 11, s = r & 2047;
                    int h = col >> 6, cc = col & 63;
                    size_t o = ((size_t)(b * NH + h) * SEQ + s) * DQK + cc;
                    uint32_t lo, hi = packsplit(va, vb, lo);
                    *(uint32_t*)(outH + o) = hi; *(uint32_t*)(outL + o) = lo;
                }
            }
        }
    }
}

// ---------------- Launch ----------------
static void run_gemm(const bf16* Ah, const bf16* Al, const bf16* Bh, const bf16* Bl,
                     const float* bias, float* C, bf16* outH, bf16* outL,
                     const int* pos, int mode,
                     int M, int N, int K, int batches,
                     int lda, int ldb, int ldc,
                     long long sAb, long long sAh, long long sBb, long long sBh,
                     long long sCb, long long sCh, float scale)
{
    mma_gemm_kernel<<<dim3(N / 64, M / 128, batches), 256, GEMM_SMEM>>>(
        Ah, Al, Bh, Bl, bias, C, outH, outL, pos, mode, K, lda, ldb, ldc,
        sAb, sAh, sBb, sBh, sCb, sCh, scale);
}

extern "C" void kernel_launch(void* const* d_in, const int* in_sizes, int n_in,
                              void* d_out, int out_size)
{
    const float* x        = (const float*)d_in[0];
    const int*   pos      = (const int*)d_in[1];
    const float* w_dq_w   = (const float*)d_in[2];
    const float* w_dq_b   = (const float*)d_in[3];
    const float* q_norm_w = (const float*)d_in[4];
    const float* w_uq_w   = (const float*)d_in[5];
    const float* w_uq_b   = (const float*)d_in[6];
    const float* w_dkv_w  = (const float*)d_in[7];
    const float* w_dkv_b  = (const float*)d_in[8];
    const float* kv_norm_w= (const float*)d_in[9];
    const float* w_ukv_w  = (const float*)d_in[10];
    const float* w_ukv_b  = (const float*)d_in[11];
    const float* w_o_w    = (const float*)d_in[12];
    const float* w_o_b    = (const float*)d_in[13];
    float* out = (float*)d_out;

    cudaFuncSetAttribute(mma_gemm_kernel, cudaFuncAttributeMaxDynamicSharedMemorySize, GEMM_SMEM);

    float *comb, *ckv, *S, *Wf, *beff, *bcomb;
    bf16 *xh, *xl, *cqh, *cql, *ckvh, *ckvl, *ckvTh, *ckvTl, *Qh, *Ql, *Kh, *Kl, *Ph, *Pl;
    bf16 *ctxh, *ctxl, *wcombh, *wcombl, *wuqh, *wuql;
    bf16 *wukvh, *wukvl, *wukvnth, *wukvntl, *woh, *wol, *WfBh, *WfBl;
    cudaGetSymbolAddress((void**)&comb, g_comb);
    cudaGetSymbolAddress((void**)&ckv, g_ckv);     cudaGetSymbolAddress((void**)&S, g_S);
    cudaGetSymbolAddress((void**)&Wf, g_Wf);
    cudaGetSymbolAddress((void**)&beff, g_bias_eff); cudaGetSymbolAddress((void**)&bcomb, g_bcomb);
    cudaGetSymbolAddress((void**)&xh, g_xh);       cudaGetSymbolAddress((void**)&xl, g_xl);
    cudaGetSymbolAddress((void**)&cqh, g_cqh);     cudaGetSymbolAddress((void**)&cql, g_cql);
    cudaGetSymbolAddress((void**)&ckvh, g_ckvh);   cudaGetSymbolAddress((void**)&ckvl, g_ckvl);
    cudaGetSymbolAddress((void**)&ckvTh, g_ckvTh); cudaGetSymbolAddress((void**)&ckvTl, g_ckvTl);
    cudaGetSymbolAddress((void**)&Qh, g_Qh);       cudaGetSymbolAddress((void**)&Ql, g_Ql);
    cudaGetSymbolAddress((void**)&Kh, g_Kh);       cudaGetSymbolAddress((void**)&Kl, g_Kl);
    cudaGetSymbolAddress((void**)&Ph, g_Ph);       cudaGetSymbolAddress((void**)&Pl, g_Pl);
    cudaGetSymbolAddress((void**)&ctxh, g_ctxh);   cudaGetSymbolAddress((void**)&ctxl, g_ctxl);
    cudaGetSymbolAddress((void**)&wcombh, g_wcombh); cudaGetSymbolAddress((void**)&wcombl, g_wcombl);
    cudaGetSymbolAddress((void**)&wuqh, g_wuqh);   cudaGetSymbolAddress((void**)&wuql, g_wuql);
    cudaGetSymbolAddress((void**)&wukvh, g_wukvh); cudaGetSymbolAddress((void**)&wukvl, g_wukvl);
    cudaGetSymbolAddress((void**)&wukvnth, g_wukvnth); cudaGetSymbolAddress((void**)&wukvntl, g_wukvntl);
    cudaGetSymbolAddress((void**)&woh, g_woh);     cudaGetSymbolAddress((void**)&wol, g_wol);
    cudaGetSymbolAddress((void**)&WfBh, g_WfBh);   cudaGetSymbolAddress((void**)&WfBl, g_WfBl);

    // ---- Operand conversions ----
    convert_split_kernel<<<(BS * DIM / 4) / 256, 256>>>(x, xh, xl, BS * DIM / 4);
    convert_split_kernel<<<(KVC * 2560 / 4 + 255) / 256, 256>>>(w_ukv_w, wukvnth, wukvntl, KVC * 2560 / 4);
    transpose_split_kernel<<<dim3(QC / 32, DIM / 32), dim3(32, 8)>>>(w_dq_w, DIM, QC, wcombh, wcombl);
    transpose_split_kernel<<<dim3((KVC + KROPE) / 32, DIM / 32), dim3(32, 8)>>>(
        w_dkv_w, DIM, KVC + KROPE, wcombh + (size_t)QC * DIM, wcombl + (size_t)QC * DIM);
    transpose_split_kernel<<<dim3((NH * DQK) / 32, QC / 32), dim3(32, 8)>>>(w_uq_w, QC, NH * DQK, wuqh, wuql);
    transpose_split_kernel<<<dim3((NH * KNOPE) / 32, KVC / 32), dim3(32, 8)>>>(w_ukv_w, KVC, NH * (KNOPE + VHD), wukvh, wukvl);
    transpose_split_kernel<<<dim3(DIM / 32, (NH * VHD) / 32), dim3(32, 8)>>>(w_o_w, NH * VHD, DIM, woh, wol);
    combine_bias_kernel<<<1, NCOMB>>>(w_dq_b, w_dkv_b);

    // ---- W_f = W_uv_h @ W_o_h  (batched over h), transpose to B layout ----
    run_gemm(wukvnth + NH * KNOPE, wukvntl + NH * KNOPE, woh, wol, nullptr, Wf, nullptr, nullptr,
             nullptr, 0,
             KVC, DIM, VHD, NH,
             NH * (KNOPE + VHD), NH * VHD, DIM,
             0, VHD, 0, VHD,
             0, (long long)KVC * DIM, 1.f);
    transpose_split_kernel<<<dim3(DIM / 32, DIM / 32), dim3(32, 8)>>>(Wf, DIM, DIM, WfBh, WfBl);
    bias_eff_kernel<<<DIM, 128>>>(w_o_w, w_o_b, w_ukv_b);

    // 1) comb = x @ [w_dq | w_dkv] + b     (N=320)
    run_gemm(xh, xl, wcombh, wcombl, bcomb, comb, nullptr, nullptr, nullptr, 0,
             BS, NCOMB, DIM, 1,
             DIM, DIM, NCOMB, 0, 0, 0, 0, 0, 0, 1.f);
    // 2) cq = rmsnorm(comb[:, :128]) -> hi/lo
    rmsnorm_split_kernel<<<BS, 128>>>(comb, NCOMB, q_norm_w, cqh, cql, nullptr);
    // 3) ckv = rmsnorm(comb[:, 128:256]) -> hi/lo + fp32
    rmsnorm_split_kernel<<<BS, 128>>>(comb + KVC, NCOMB, kv_norm_w, ckvh, ckvl, ckv);
    // 3b) ckvT for ctx GEMM
    ckvt_split_kernel<<<dim3(KVC / 32, SEQ / 32, BATCH), dim3(32, 8)>>>();
    // 4) Q = rope(cq @ w_uq + b) * scale  -> scattered bf16 hi/lo (fused epilogue)
    run_gemm(cqh, cql, wuqh, wuql, w_uq_b, nullptr, Qh, Ql, pos, 2,
             BS, NH * DQK, QC, 1,
             QC, QC, 0, 0, 0, 0, 0, 0, 0, 1.f);
    // 5) K-nope = ckv @ w_uk + b  -> scattered bf16 hi/lo (fused epilogue)
    run_gemm(ckvh, ckvl, wukvh, wukvl, w_ukv_b, nullptr, Kh, Kl, nullptr, 3,
             BS, NH * KNOPE, KVC, 1,
             KVC, KVC, 0, 0, 0, 0, 0, 0, 0, 1.f);
    // 6) K rope (cols 64-127, broadcast heads)
    assemble_krope_kernel<<<dim3(SEQ, BATCH), KROPE>>>(pos);
    // 7) S = Q @ K^T (fp32, R13-proven)
    run_gemm(Qh, Ql, Kh, Kl, nullptr, S, nullptr, nullptr, nullptr, 0,
             SEQ, SEQ, DQK, BATCH * NH,
             DQK, DQK, SEQ,
             8LL * SEQ * DQK, (long long)SEQ * DQK,
             8LL * SEQ * DQK, (long long)SEQ * DQK,
             8LL * SEQ * SEQ, (long long)SEQ * SEQ, 1.f);
    // 8) P = softmax(S) -> hi/lo
    softmax_split_kernel<<<16 * SEQ, 256>>>();
    // 9) ctx = P @ ckv -> bf16 hi/lo directly
    run_gemm(Ph, Pl, ckvTh, ckvTl, nullptr, nullptr, ctxh, ctxl, nullptr, 1,
             SEQ, KVC, SEQ, BATCH * NH,
             SEQ, SEQ, NH * KVC,
             8LL * SEQ * SEQ, (long long)SEQ * SEQ,
             (long long)KVC * SEQ, 0,
             (long long)SEQ * NH * KVC, KVC, 1.f);
    // 10) out = ctx @ W_f + bias_eff
    run_gemm(ctxh, ctxl, WfBh, WfBl, beff, out, nullptr, nullptr, nullptr, 0,
             BS, DIM, NH * KVC, 1,
             NH * KVC, NH * KVC, DIM, 0, 0, 0, 0, 0, 0, 1.f);
}